// round 6
// baseline (speedup 1.0000x reference)
#include <cuda_runtime.h>

#define Nn 50000
#define Hh 128
#define Ee 500000
#define TK 16
#define LDP 132   // padded pitch for shared tiles
#define NBLK 196  // ceil(Nn/256)

typedef unsigned long long u64;

// Scratch (device globals: no allocation allowed)
__device__ float g_aggr[(size_t)Nn * Hh];
__device__ float g_h1[(size_t)Nn * Hh];
__device__ int   g_head[Nn];   // per-node list head (-1 = empty)
__device__ u64   g_link[Ee];   // (src << 32) | next  (next = 0xFFFFFFFF ends)

// ---------------------------------------------------------------------------
// Linked-list build: head init + one-pass atomicExch chain
// ---------------------------------------------------------------------------
__global__ void init_head_kernel() {
    int i = blockIdx.x * 256 + threadIdx.x;
    if (i < Nn) g_head[i] = -1;
}

__global__ void build_kernel(const int* __restrict__ edge) {
    int e = blockIdx.x * 256 + threadIdx.x;
    if (e < Ee) {
        int dst = __ldg(edge + e);        // edge_index[0][e]
        int src = __ldg(edge + Ee + e);   // edge_index[1][e]
        int prev = atomicExch(&g_head[dst], e);
        g_link[e] = ((u64)(unsigned)src << 32) | (unsigned)prev;
    }
}

// ---------------------------------------------------------------------------
// Gather-reduce: one warp per node walks its list. Each step is ONE dependent
// 8B load (src+next packed); the 512B x-row gathers overlap freely.
// ---------------------------------------------------------------------------
__global__ void aggregate_kernel(const float* __restrict__ x) {
    int n = blockIdx.x * 8 + (threadIdx.x >> 5);
    if (n >= Nn) return;
    int lane = threadIdx.x & 31;
    float4 acc = make_float4(0.f, 0.f, 0.f, 0.f);
    int e = g_head[n];
    while (e != -1) {
        u64 pk = __ldg(g_link + e);
        int src = (int)(pk >> 32);
        e = (int)(unsigned)pk;            // 0xFFFFFFFF -> -1
        float4 v = *reinterpret_cast<const float4*>(x + (size_t)src * Hh + lane * 4);
        acc.x += v.x; acc.y += v.y; acc.z += v.z; acc.w += v.w;
    }
    *reinterpret_cast<float4*>(g_aggr + (size_t)n * Hh + lane * 4) = acc;
}

// ---------------------------------------------------------------------------
// Tiled SGEMM (R1 plain-FFMA version — measured fastest):
//   C[M,128] = act( A0 @ W0^T + (A1 @ (W1a+W1b)^T) + biases )
//   128x128 output tile per block, TK=16 k-chunk, 256 threads, 8x8 microtile
// ---------------------------------------------------------------------------
__global__ __launch_bounds__(256, 2) void gemm_kernel(
    const float* __restrict__ A0, const float* __restrict__ W0,
    const float* __restrict__ A1, const float* __restrict__ W1a,
    const float* __restrict__ W1b,
    const float* __restrict__ ba, const float* __restrict__ bb,
    const float* __restrict__ bc,
    float* __restrict__ C, int M, int do_relu)
{
    __shared__ __align__(16) float As[TK * LDP];
    __shared__ __align__(16) float Bs[TK * LDP];

    const int tid = threadIdx.x;
    const int ty = tid >> 4;        // 0..15
    const int tx = tid & 15;        // 0..15
    const int m0 = ty * 8;
    const int n0 = tx * 8;
    const int bm = blockIdx.x * 128;

    float acc[8][8];
    #pragma unroll
    for (int i = 0; i < 8; i++)
        #pragma unroll
        for (int j = 0; j < 8; j++) acc[i][j] = 0.f;

    const int nseg = (A1 != nullptr) ? 2 : 1;
    for (int seg = 0; seg < nseg; seg++) {
        const float* A  = seg ? A1 : A0;
        const float* Wa = seg ? W1a : W0;
        const float* Wb = seg ? W1b : nullptr;

        for (int kk = 0; kk < 128; kk += TK) {
            // ---- load A tile (transposed into As[k][m]) + B tile Bs[k][n] ----
            #pragma unroll
            for (int q = 0; q < 2; q++) {
                int l = q * 256 + tid;     // 0..511
                int row = l >> 2;          // 0..127
                int kq = (l & 3) * 4;      // 0,4,8,12

                float4 va = make_float4(0.f, 0.f, 0.f, 0.f);
                if (bm + row < M)
                    va = *reinterpret_cast<const float4*>(
                        A + (size_t)(bm + row) * 128 + kk + kq);
                As[(kq + 0) * LDP + row] = va.x;
                As[(kq + 1) * LDP + row] = va.y;
                As[(kq + 2) * LDP + row] = va.z;
                As[(kq + 3) * LDP + row] = va.w;

                float4 vb = *reinterpret_cast<const float4*>(
                    Wa + (size_t)row * 128 + kk + kq);
                if (Wb) {
                    float4 v2 = *reinterpret_cast<const float4*>(
                        Wb + (size_t)row * 128 + kk + kq);
                    vb.x += v2.x; vb.y += v2.y; vb.z += v2.z; vb.w += v2.w;
                }
                Bs[(kq + 0) * LDP + row] = vb.x;
                Bs[(kq + 1) * LDP + row] = vb.y;
                Bs[(kq + 2) * LDP + row] = vb.z;
                Bs[(kq + 3) * LDP + row] = vb.w;
            }
            __syncthreads();

            // ---- compute ----
            #pragma unroll
            for (int k = 0; k < TK; k++) {
                float a[8], b[8];
                float4 t;
                t = *reinterpret_cast<float4*>(&As[k * LDP + m0]);
                a[0] = t.x; a[1] = t.y; a[2] = t.z; a[3] = t.w;
                t = *reinterpret_cast<float4*>(&As[k * LDP + m0 + 4]);
                a[4] = t.x; a[5] = t.y; a[6] = t.z; a[7] = t.w;
                t = *reinterpret_cast<float4*>(&Bs[k * LDP + n0]);
                b[0] = t.x; b[1] = t.y; b[2] = t.z; b[3] = t.w;
                t = *reinterpret_cast<float4*>(&Bs[k * LDP + n0 + 4]);
                b[4] = t.x; b[5] = t.y; b[6] = t.z; b[7] = t.w;
                #pragma unroll
                for (int i = 0; i < 8; i++)
                    #pragma unroll
                    for (int j = 0; j < 8; j++)
                        acc[i][j] = fmaf(a[i], b[j], acc[i][j]);
            }
            __syncthreads();
        }
    }

    // ---- epilogue: bias + optional relu, float4 stores ----
    float bias[8];
    #pragma unroll
    for (int j = 0; j < 8; j++) {
        float s = 0.f;
        if (ba) s += __ldg(ba + n0 + j);
        if (bb) s += __ldg(bb + n0 + j);
        if (bc) s += __ldg(bc + n0 + j);
        bias[j] = s;
    }
    #pragma unroll
    for (int i = 0; i < 8; i++) {
        int row = bm + m0 + i;
        if (row < M) {
            float v[8];
            #pragma unroll
            for (int j = 0; j < 8; j++) {
                float x = acc[i][j] + bias[j];
                v[j] = do_relu ? fmaxf(x, 0.f) : x;
            }
            float4 o0 = make_float4(v[0], v[1], v[2], v[3]);
            float4 o1 = make_float4(v[4], v[5], v[6], v[7]);
            *reinterpret_cast<float4*>(C + (size_t)row * 128 + n0)     = o0;
            *reinterpret_cast<float4*>(C + (size_t)row * 128 + n0 + 4) = o1;
        }
    }
}

// ---------------------------------------------------------------------------
// Launch: only the h_a branch matters — h_b in the reference is dead code.
// out = (relu(aggr_ba @ wl.T + x_a @ (w0+w1).T + biases)) @ out_w.T + out_b
// ---------------------------------------------------------------------------
extern "C" void kernel_launch(void* const* d_in, const int* in_sizes, int n_in,
                              void* d_out, int out_size) {
    const float* x_a     = (const float*)d_in[0];
    const int*   edge_ba = (const int*)d_in[3];
    const float* c1_w0_w = (const float*)d_in[10];
    const float* c1_w0_b = (const float*)d_in[11];
    const float* c1_wl_w = (const float*)d_in[12];
    const float* c1_wl_b = (const float*)d_in[13];
    const float* c1_w1_w = (const float*)d_in[14];
    const float* c1_w1_b = (const float*)d_in[15];
    const float* out_w   = (const float*)d_in[16];
    const float* out_b   = (const float*)d_in[17];
    float* out = (float*)d_out;

    float *aggr_p = nullptr, *h1_p = nullptr;
    cudaGetSymbolAddress((void**)&aggr_p, g_aggr);
    cudaGetSymbolAddress((void**)&h1_p, g_h1);

    const int egrid = (Ee + 255) / 256;   // 1954

    // Linked-list build (2 launches)
    init_head_kernel<<<NBLK, 256>>>();
    build_kernel<<<egrid, 256>>>(edge_ba);

    // Gather-reduce into aggr
    aggregate_kernel<<<(Nn + 7) / 8, 256>>>(x_a);

    const int grid = (Nn + 127) / 128;  // 391 blocks

    // h1 = relu(aggr @ wl.T + x_a @ (w0+w1).T + (bl+b0+b1))
    gemm_kernel<<<grid, 256>>>(aggr_p, c1_wl_w,
                               x_a, c1_w0_w, c1_w1_w,
                               c1_wl_b, c1_w0_b, c1_w1_b,
                               h1_p, Nn, 1);

    // out = h1 @ out_w.T + out_b
    gemm_kernel<<<grid, 256>>>(h1_p, out_w,
                               nullptr, nullptr, nullptr,
                               out_b, nullptr, nullptr,
                               out, Nn, 0);
}

// round 8
// speedup vs baseline: 1.3114x; 1.3114x over previous
#include <cuda_runtime.h>
#include <cuda_bf16.h>
#include <cstdint>

#define Nn 50000
#define Hh 128
#define Ee 500000
#define NBLK 196  // ceil(Nn/256)

typedef unsigned long long u64;
typedef unsigned int u32;

// ---------------------------------------------------------------------------
// Scratch (device globals: no allocation allowed)
// ---------------------------------------------------------------------------
__device__ int g_head[Nn];
__device__ u64 g_link[Ee];
// bf16 hi/lo operand images, packed 2 bf16 per u32 (memory order: even col low)
__device__ u32 g_ah[(size_t)Nn * 64];   // aggr hi
__device__ u32 g_al[(size_t)Nn * 64];   // aggr lo
__device__ u32 g_xh[(size_t)Nn * 64];   // x_a hi
__device__ u32 g_xl[(size_t)Nn * 64];   // x_a lo
__device__ u32 g_h1h[(size_t)Nn * 64];  // h1 hi
__device__ u32 g_h1l[(size_t)Nn * 64];  // h1 lo
// Weights, TRANSPOSED row-major: Wt[k*128 + n] = W[n][k]. 0=Wl, 1=W0+W1, 2=Wout
__device__ unsigned short g_wt_hi[3][16384];
__device__ unsigned short g_wt_lo[3][16384];

// ---------------------------------------------------------------------------
// helpers
// ---------------------------------------------------------------------------
__device__ __forceinline__ u32 smem_u32(const void* p) {
    u32 a;
    asm("{ .reg .u64 t; cvta.to.shared.u64 t, %1; cvt.u32.u64 %0, t; }"
        : "=r"(a) : "l"(p));
    return a;
}
__device__ __forceinline__ void split2(float a, float b, u32& hi, u32& lo) {
    __nv_bfloat16 ha = __float2bfloat16(a), hb = __float2bfloat16(b);
    hi = (u32)__bfloat16_as_ushort(ha) | ((u32)__bfloat16_as_ushort(hb) << 16);
    __nv_bfloat16 la = __float2bfloat16(a - __bfloat162float(ha));
    __nv_bfloat16 lb = __float2bfloat16(b - __bfloat162float(hb));
    lo = (u32)__bfloat16_as_ushort(la) | ((u32)__bfloat16_as_ushort(lb) << 16);
}

#define LDMX4(r, addr) \
    asm volatile("ldmatrix.sync.aligned.m8n8.x4.shared.b16 {%0,%1,%2,%3}, [%4];" \
        : "=r"((r)[0]), "=r"((r)[1]), "=r"((r)[2]), "=r"((r)[3]) : "r"(addr))
#define LDMX4T(r, addr) \
    asm volatile("ldmatrix.sync.aligned.m8n8.x4.trans.shared.b16 {%0,%1,%2,%3}, [%4];" \
        : "=r"((r)[0]), "=r"((r)[1]), "=r"((r)[2]), "=r"((r)[3]) : "r"(addr))
#define MMA(c, a, b0, b1) \
    asm volatile("mma.sync.aligned.m16n8k16.row.col.f32.bf16.bf16.f32 " \
        "{%0,%1,%2,%3},{%4,%5,%6,%7},{%8,%9},{%0,%1,%2,%3};" \
        : "+f"((c)[0]), "+f"((c)[1]), "+f"((c)[2]), "+f"((c)[3]) \
        : "r"((a)[0]), "r"((a)[1]), "r"((a)[2]), "r"((a)[3]), "r"(b0), "r"(b1))

// ---------------------------------------------------------------------------
// Graph phase (unchanged structure; aggregate now emits bf16 hi/lo)
// ---------------------------------------------------------------------------
__global__ void init_head_kernel() {
    int i = blockIdx.x * 256 + threadIdx.x;
    if (i < Nn) g_head[i] = -1;
}
__global__ void build_kernel(const int* __restrict__ edge) {
    int e = blockIdx.x * 256 + threadIdx.x;
    if (e < Ee) {
        int dst = __ldg(edge + e);
        int src = __ldg(edge + Ee + e);
        int prev = atomicExch(&g_head[dst], e);
        g_link[e] = ((u64)(unsigned)src << 32) | (unsigned)prev;
    }
}
__global__ void aggregate_kernel(const float* __restrict__ x) {
    int n = blockIdx.x * 8 + (threadIdx.x >> 5);
    if (n >= Nn) return;
    int lane = threadIdx.x & 31;
    float4 acc = make_float4(0.f, 0.f, 0.f, 0.f);
    int e = g_head[n];
    while (e != -1) {
        u64 pk = __ldg(g_link + e);
        int src = (int)(pk >> 32);
        e = (int)(unsigned)pk;
        float4 v = *reinterpret_cast<const float4*>(x + (size_t)src * Hh + lane * 4);
        acc.x += v.x; acc.y += v.y; acc.z += v.z; acc.w += v.w;
    }
    u32 h0, l0, h1, l1;
    split2(acc.x, acc.y, h0, l0);
    split2(acc.z, acc.w, h1, l1);
    size_t o = (size_t)n * 64 + lane * 2;
    g_ah[o] = h0; g_ah[o + 1] = h1;
    g_al[o] = l0; g_al[o + 1] = l1;
}
// split x_a into bf16 hi/lo
__global__ void xsplit_kernel(const float* __restrict__ x) {
    size_t i = (size_t)blockIdx.x * 256 + threadIdx.x;   // pair index
    if (i >= (size_t)Nn * 64) return;
    float2 v = *reinterpret_cast<const float2*>(x + i * 2);
    u32 h, l;
    split2(v.x, v.y, h, l);
    g_xh[i] = h; g_xl[i] = l;
}
// weights: transpose + hi/lo split. l = k*128 + n; W row-major [n][k].
__global__ void wprep_kernel(const float* __restrict__ wl,
                             const float* __restrict__ w0,
                             const float* __restrict__ w1,
                             const float* __restrict__ wout) {
    int i = blockIdx.x * 256 + threadIdx.x;
    if (i >= 3 * 16384) return;
    int mat = i >> 14;
    int l = i & 16383;
    int k = l >> 7, n = l & 127;
    int src = n * 128 + k;
    float v = (mat == 0) ? __ldg(wl + src)
            : (mat == 1) ? __ldg(w0 + src) + __ldg(w1 + src)
                         : __ldg(wout + src);
    __nv_bfloat16 hb = __float2bfloat16(v);
    g_wt_hi[mat][l] = __bfloat16_as_ushort(hb);
    g_wt_lo[mat][l] = __bfloat16_as_ushort(__float2bfloat16(v - __bfloat162float(hb)));
}

// ---------------------------------------------------------------------------
// Tensor-core GEMM (mma.sync bf16, split precision):
//   C[M,128] = act( sum_seg A_seg @ W_seg^T + bias ),  A,W split hi/lo,
//   computed as Ah@Wh + Ah@Wl + Al@Wh with fp32 accumulation.
// Block: 128x128 tile, 256 threads = 8 warps (warp tile 32m x 64n).
// W (transposed, [k][n]) resident in SMEM per segment; A chunked per k16.
// mode 1: relu, write split bf16 h1.  mode 0: write fp32 + bias.
// ---------------------------------------------------------------------------
#define SMB_BIAS 0        // 512 B (128 f32)
#define SMB_AH   512      // 128 rows x 48 B
#define SMB_AL   6656
#define SMB_WH   12800    // 128 k-rows x 272 B
#define SMB_WL   47616
#define SMB_TOT  82432
#define APITCH   48
#define WPITCH   272

__global__ __launch_bounds__(256, 2) void tc_gemm(
    const u32* __restrict__ A0h, const u32* __restrict__ A0l,
    const u32* __restrict__ A1h, const u32* __restrict__ A1l,
    int mat0, int mat1, int nseg,
    const float* __restrict__ ba, const float* __restrict__ bb,
    const float* __restrict__ bc,
    float* __restrict__ outf, u32* __restrict__ outh, u32* __restrict__ outl,
    int mode, int M)
{
    extern __shared__ __align__(16) char smem[];
    const u32 sb = smem_u32(smem);
    float* bias_s = reinterpret_cast<float*>(smem + SMB_BIAS);

    const int tid = threadIdx.x;
    const int w = tid >> 5, lane = tid & 31;
    const int mw = (w & 3) * 32, nw = (w >> 2) * 64;
    const int bm = blockIdx.x * 128;

    if (tid < 128) {
        float s = __ldg(ba + tid);
        if (bb) s += __ldg(bb + tid);
        if (bc) s += __ldg(bc + tid);
        bias_s[tid] = s;
    }

    // lane-constant address pieces
    const u32 aoff = (u32)((mw + (lane & 15)) * APITCH + (lane >> 4) * 16);
    const int wg = lane >> 3, wi = lane & 7;
    const u32 wkoff = (u32)(((wg & 1) * 8 + wi) * WPITCH);
    const u32 wnoff = (u32)((nw + (wg >> 1) * 8) * 2);

    float c[2][8][4];
    #pragma unroll
    for (int mg = 0; mg < 2; mg++)
        #pragma unroll
        for (int nf = 0; nf < 8; nf++)
            #pragma unroll
            for (int q = 0; q < 4; q++) c[mg][nf][q] = 0.f;

    #pragma unroll 1
    for (int seg = 0; seg < nseg; seg++) {
        const u32* Ah = seg ? A1h : A0h;
        const u32* Al = seg ? A1l : A0l;
        const int mat = seg ? mat1 : mat0;

        __syncthreads();   // previous compute done before W overwrite
        {   // stage W hi/lo: 2048 16B units each; unit u: k=u>>4, c16=u&15
            const uint4* sh = reinterpret_cast<const uint4*>(g_wt_hi[mat]);
            const uint4* sl = reinterpret_cast<const uint4*>(g_wt_lo[mat]);
            #pragma unroll
            for (int q = 0; q < 8; q++) {
                int u = q * 256 + tid;
                int kk = u >> 4, c16 = u & 15;
                *reinterpret_cast<uint4*>(smem + SMB_WH + kk * WPITCH + c16 * 16) = sh[u];
                *reinterpret_cast<uint4*>(smem + SMB_WL + kk * WPITCH + c16 * 16) = sl[u];
            }
        }

        #pragma unroll 1
        for (int kc = 0; kc < 8; kc++) {
            __syncthreads();
            {   // stage A chunk: 128 rows x 16 k (bf16) per version
                int r = tid >> 1, h = tid & 1;
                int grow = bm + r;
                uint4 vh = make_uint4(0, 0, 0, 0), vl = make_uint4(0, 0, 0, 0);
                if (grow < M) {
                    size_t idx = (size_t)grow * 16 + kc * 2 + h;
                    vh = reinterpret_cast<const uint4*>(Ah)[idx];
                    vl = reinterpret_cast<const uint4*>(Al)[idx];
                }
                *reinterpret_cast<uint4*>(smem + SMB_AH + r * APITCH + h * 16) = vh;
                *reinterpret_cast<uint4*>(smem + SMB_AL + r * APITCH + h * 16) = vl;
            }
            __syncthreads();

            u32 ah[2][4], al_[2][4];
            #pragma unroll
            for (int mg = 0; mg < 2; mg++) {
                LDMX4(ah[mg],  sb + SMB_AH + aoff + mg * 16 * APITCH);
                LDMX4(al_[mg], sb + SMB_AL + aoff + mg * 16 * APITCH);
            }
            u32 bw[4][4];
            const u32 wko = (u32)(kc * 16 * WPITCH) + wkoff;
            #pragma unroll
            for (int nf = 0; nf < 4; nf++)
                LDMX4T(bw[nf], sb + SMB_WH + wko + wnoff + nf * 32);
            #pragma unroll
            for (int mg = 0; mg < 2; mg++)
                #pragma unroll
                for (int nf = 0; nf < 4; nf++) {
                    MMA(c[mg][2 * nf],     ah[mg],  bw[nf][0], bw[nf][1]);
                    MMA(c[mg][2 * nf + 1], ah[mg],  bw[nf][2], bw[nf][3]);
                    MMA(c[mg][2 * nf],     al_[mg], bw[nf][0], bw[nf][1]);
                    MMA(c[mg][2 * nf + 1], al_[mg], bw[nf][2], bw[nf][3]);
                }
            #pragma unroll
            for (int nf = 0; nf < 4; nf++)
                LDMX4T(bw[nf], sb + SMB_WL + wko + wnoff + nf * 32);
            #pragma unroll
            for (int mg = 0; mg < 2; mg++)
                #pragma unroll
                for (int nf = 0; nf < 4; nf++) {
                    MMA(c[mg][2 * nf],     ah[mg], bw[nf][0], bw[nf][1]);
                    MMA(c[mg][2 * nf + 1], ah[mg], bw[nf][2], bw[nf][3]);
                }
        }
    }

    // ---- epilogue ----
    const int r0 = (lane >> 2);
    const int cb = 2 * (lane & 3);
    #pragma unroll
    for (int mg = 0; mg < 2; mg++) {
        #pragma unroll
        for (int nf = 0; nf < 8; nf++) {
            int col = nw + nf * 8 + cb;
            int rowA = bm + mw + mg * 16 + r0;
            int rowB = rowA + 8;
            float b0 = bias_s[col], b1 = bias_s[col + 1];
            if (mode) {
                float h00 = fmaxf(c[mg][nf][0] + b0, 0.f);
                float h01 = fmaxf(c[mg][nf][1] + b1, 0.f);
                float h10 = fmaxf(c[mg][nf][2] + b0, 0.f);
                float h11 = fmaxf(c[mg][nf][3] + b1, 0.f);
                u32 hi, lo;
                if (rowA < M) {
                    split2(h00, h01, hi, lo);
                    outh[(size_t)rowA * 64 + (col >> 1)] = hi;
                    outl[(size_t)rowA * 64 + (col >> 1)] = lo;
                }
                if (rowB < M) {
                    split2(h10, h11, hi, lo);
                    outh[(size_t)rowB * 64 + (col >> 1)] = hi;
                    outl[(size_t)rowB * 64 + (col >> 1)] = lo;
                }
            } else {
                if (rowA < M)
                    *reinterpret_cast<float2*>(outf + (size_t)rowA * 128 + col) =
                        make_float2(c[mg][nf][0] + b0, c[mg][nf][1] + b1);
                if (rowB < M)
                    *reinterpret_cast<float2*>(outf + (size_t)rowB * 128 + col) =
                        make_float2(c[mg][nf][2] + b0, c[mg][nf][3] + b1);
            }
        }
    }
}

// ---------------------------------------------------------------------------
// Launch: only the h_a branch matters — h_b in the reference is dead code.
// out = (relu(aggr_ba @ wl.T + x_a @ (w0+w1).T + biases)) @ out_w.T + out_b
// ---------------------------------------------------------------------------
extern "C" void kernel_launch(void* const* d_in, const int* in_sizes, int n_in,
                              void* d_out, int out_size) {
    const float* x_a     = (const float*)d_in[0];
    const int*   edge_ba = (const int*)d_in[3];
    const float* c1_w0_w = (const float*)d_in[10];
    const float* c1_w0_b = (const float*)d_in[11];
    const float* c1_wl_w = (const float*)d_in[12];
    const float* c1_wl_b = (const float*)d_in[13];
    const float* c1_w1_w = (const float*)d_in[14];
    const float* c1_w1_b = (const float*)d_in[15];
    const float* out_w   = (const float*)d_in[16];
    const float* out_b   = (const float*)d_in[17];
    float* out = (float*)d_out;

    u32 *ah, *al, *xh, *xl, *h1h, *h1l;
    cudaGetSymbolAddress((void**)&ah, g_ah);
    cudaGetSymbolAddress((void**)&al, g_al);
    cudaGetSymbolAddress((void**)&xh, g_xh);
    cudaGetSymbolAddress((void**)&xl, g_xl);
    cudaGetSymbolAddress((void**)&h1h, g_h1h);
    cudaGetSymbolAddress((void**)&h1l, g_h1l);

    const int egrid = (Ee + 255) / 256;

    // graph + operand prep
    init_head_kernel<<<NBLK, 256>>>();
    build_kernel<<<egrid, 256>>>(edge_ba);
    wprep_kernel<<<(3 * 16384 + 255) / 256, 256>>>(c1_wl_w, c1_w0_w, c1_w1_w, out_w);
    xsplit_kernel<<<(int)(((size_t)Nn * 64 + 255) / 256), 256>>>(x_a);
    aggregate_kernel<<<(Nn + 7) / 8, 256>>>(x_a);

    cudaFuncSetAttribute(tc_gemm, cudaFuncAttributeMaxDynamicSharedMemorySize, SMB_TOT);
    const int grid = (Nn + 127) / 128;  // 391

    // h1 = relu(aggr @ Wl^T + x_a @ (W0+W1)^T + bias) -> split bf16
    tc_gemm<<<grid, 256, SMB_TOT>>>(ah, al, xh, xl, 0, 1, 2,
                                    c1_wl_b, c1_w0_b, c1_w1_b,
                                    nullptr, h1h, h1l, 1, Nn);
    // out = h1 @ Wout^T + out_b (fp32)
    tc_gemm<<<grid, 256, SMB_TOT>>>(h1h, h1l, nullptr, nullptr, 2, 2, 1,
                                    out_b, nullptr, nullptr,
                                    out, nullptr, nullptr, 0, Nn);
}

// round 9
// speedup vs baseline: 1.3936x; 1.0627x over previous
#include <cuda_runtime.h>
#include <cuda_bf16.h>
#include <cstdint>

#define Nn 50000
#define Hh 128
#define Ee 500000
#define NBLK 196  // ceil(Nn/256)

// fused prep kernel block ranges
#define PB_BUILD  1954                 // ceil(Ee/256)
#define PB_XSPLIT 3125                 // Nn*64/4/256
#define PB_WPREP  192                  // 3*16384/256
#define PB_TOTAL  (PB_BUILD + PB_XSPLIT + PB_WPREP)

typedef unsigned long long u64;
typedef unsigned int u32;

// ---------------------------------------------------------------------------
// Scratch (device globals: no allocation allowed)
// ---------------------------------------------------------------------------
__device__ int g_head[Nn];
__device__ u64 g_link[Ee];
// bf16 hi/lo operand images, packed 2 bf16 per u32 (memory order: even col low)
__device__ u32 g_ah[(size_t)Nn * 64];   // aggr hi
__device__ u32 g_al[(size_t)Nn * 64];   // aggr lo
__device__ u32 g_xh[(size_t)Nn * 64];   // x_a hi
__device__ u32 g_xl[(size_t)Nn * 64];   // x_a lo
__device__ u32 g_h1h[(size_t)Nn * 64];  // h1 hi
__device__ u32 g_h1l[(size_t)Nn * 64];  // h1 lo
// Weights, TRANSPOSED row-major: Wt[k*128 + n] = W[n][k]. 0=Wl, 1=W0+W1, 2=Wout
__device__ unsigned short g_wt_hi[3][16384];
__device__ unsigned short g_wt_lo[3][16384];

// ---------------------------------------------------------------------------
// helpers
// ---------------------------------------------------------------------------
__device__ __forceinline__ u32 smem_u32(const void* p) {
    u32 a;
    asm("{ .reg .u64 t; cvta.to.shared.u64 t, %1; cvt.u32.u64 %0, t; }"
        : "=r"(a) : "l"(p));
    return a;
}
__device__ __forceinline__ void split2(float a, float b, u32& hi, u32& lo) {
    __nv_bfloat16 ha = __float2bfloat16(a), hb = __float2bfloat16(b);
    hi = (u32)__bfloat16_as_ushort(ha) | ((u32)__bfloat16_as_ushort(hb) << 16);
    __nv_bfloat16 la = __float2bfloat16(a - __bfloat162float(ha));
    __nv_bfloat16 lb = __float2bfloat16(b - __bfloat162float(hb));
    lo = (u32)__bfloat16_as_ushort(la) | ((u32)__bfloat16_as_ushort(lb) << 16);
}

#define LDMX4(r, addr) \
    asm volatile("ldmatrix.sync.aligned.m8n8.x4.shared.b16 {%0,%1,%2,%3}, [%4];" \
        : "=r"((r)[0]), "=r"((r)[1]), "=r"((r)[2]), "=r"((r)[3]) : "r"(addr))
#define LDMX4T(r, addr) \
    asm volatile("ldmatrix.sync.aligned.m8n8.x4.trans.shared.b16 {%0,%1,%2,%3}, [%4];" \
        : "=r"((r)[0]), "=r"((r)[1]), "=r"((r)[2]), "=r"((r)[3]) : "r"(addr))
#define MMA(c, a, b0, b1) \
    asm volatile("mma.sync.aligned.m16n8k16.row.col.f32.bf16.bf16.f32 " \
        "{%0,%1,%2,%3},{%4,%5,%6,%7},{%8,%9},{%0,%1,%2,%3};" \
        : "+f"((c)[0]), "+f"((c)[1]), "+f"((c)[2]), "+f"((c)[3]) \
        : "r"((a)[0]), "r"((a)[1]), "r"((a)[2]), "r"((a)[3]), "r"(b0), "r"(b1))

// ---------------------------------------------------------------------------
// init heads
// ---------------------------------------------------------------------------
__global__ void init_head_kernel() {
    int i = blockIdx.x * 256 + threadIdx.x;
    if (i < Nn) g_head[i] = -1;
}

// ---------------------------------------------------------------------------
// Fused prep: build linked list ∥ split x_a ∥ weight transpose+split.
// Independent outputs -> safe to run concurrently in one grid.
// ---------------------------------------------------------------------------
__global__ void prep_kernel(const int* __restrict__ edge,
                            const float* __restrict__ x,
                            const float* __restrict__ wl,
                            const float* __restrict__ w0,
                            const float* __restrict__ w1,
                            const float* __restrict__ wout) {
    int b = blockIdx.x;
    int tid = threadIdx.x;
    if (b < PB_BUILD) {
        // ---- edge linked-list build ----
        int e = b * 256 + tid;
        if (e < Ee) {
            int dst = __ldg(edge + e);
            int src = __ldg(edge + Ee + e);
            int prev = atomicExch(&g_head[dst], e);
            g_link[e] = ((u64)(unsigned)src << 32) | (unsigned)prev;
        }
    } else if (b < PB_BUILD + PB_XSPLIT) {
        // ---- x_a hi/lo split: 4 bf16-pairs (8 floats) per thread ----
        size_t t = (size_t)(b - PB_BUILD) * 256 + tid;   // 0 .. 800k-1
        const float4* xp = reinterpret_cast<const float4*>(x) + t * 2;
        float4 v0 = __ldg(xp);
        float4 v1 = __ldg(xp + 1);
        uint4 h, l;
        split2(v0.x, v0.y, h.x, l.x);
        split2(v0.z, v0.w, h.y, l.y);
        split2(v1.x, v1.y, h.z, l.z);
        split2(v1.z, v1.w, h.w, l.w);
        reinterpret_cast<uint4*>(g_xh)[t] = h;
        reinterpret_cast<uint4*>(g_xl)[t] = l;
    } else {
        // ---- weight transpose + hi/lo split ----
        int i = (b - PB_BUILD - PB_XSPLIT) * 256 + tid;
        int mat = i >> 14;
        int l = i & 16383;
        int k = l >> 7, n = l & 127;
        int src = n * 128 + k;
        float v = (mat == 0) ? __ldg(wl + src)
                : (mat == 1) ? __ldg(w0 + src) + __ldg(w1 + src)
                             : __ldg(wout + src);
        __nv_bfloat16 hb = __float2bfloat16(v);
        g_wt_hi[mat][l] = __bfloat16_as_ushort(hb);
        g_wt_lo[mat][l] =
            __bfloat16_as_ushort(__float2bfloat16(v - __bfloat162float(hb)));
    }
}

// ---------------------------------------------------------------------------
// Gather-reduce: one warp per node walks its list; emits bf16 hi/lo.
// ---------------------------------------------------------------------------
__global__ void aggregate_kernel(const float* __restrict__ x) {
    int n = blockIdx.x * 8 + (threadIdx.x >> 5);
    if (n >= Nn) return;
    int lane = threadIdx.x & 31;
    float4 acc = make_float4(0.f, 0.f, 0.f, 0.f);
    int e = g_head[n];
    while (e != -1) {
        u64 pk = __ldg(g_link + e);
        int src = (int)(pk >> 32);
        e = (int)(unsigned)pk;
        float4 v = *reinterpret_cast<const float4*>(x + (size_t)src * Hh + lane * 4);
        acc.x += v.x; acc.y += v.y; acc.z += v.z; acc.w += v.w;
    }
    u32 h0, l0, h1, l1;
    split2(acc.x, acc.y, h0, l0);
    split2(acc.z, acc.w, h1, l1);
    size_t o = (size_t)n * 64 + lane * 2;
    g_ah[o] = h0; g_ah[o + 1] = h1;
    g_al[o] = l0; g_al[o + 1] = l1;
}

// ---------------------------------------------------------------------------
// Tensor-core GEMM (mma.sync bf16, split precision):
//   C[M,128] = act( sum_seg A_seg @ W_seg^T + bias ),  A,W split hi/lo,
//   computed as Ah@Wh + Ah@Wl + Al@Wh with fp32 accumulation.
// Block: 128x128 tile, 256 threads = 8 warps (warp tile 32m x 64n).
// W (transposed, [k][n]) resident in SMEM per segment; A chunked per k16.
// mode 1: relu, write split bf16 h1.  mode 0: write fp32 + bias.
// ---------------------------------------------------------------------------
#define SMB_BIAS 0        // 512 B (128 f32)
#define SMB_AH   512      // 128 rows x 48 B
#define SMB_AL   6656
#define SMB_WH   12800    // 128 k-rows x 272 B
#define SMB_WL   47616
#define SMB_TOT  82432
#define APITCH   48
#define WPITCH   272

__global__ __launch_bounds__(256, 2) void tc_gemm(
    const u32* __restrict__ A0h, const u32* __restrict__ A0l,
    const u32* __restrict__ A1h, const u32* __restrict__ A1l,
    int mat0, int mat1, int nseg,
    const float* __restrict__ ba, const float* __restrict__ bb,
    const float* __restrict__ bc,
    float* __restrict__ outf, u32* __restrict__ outh, u32* __restrict__ outl,
    int mode, int M)
{
    extern __shared__ __align__(16) char smem[];
    const u32 sb = smem_u32(smem);
    float* bias_s = reinterpret_cast<float*>(smem + SMB_BIAS);

    const int tid = threadIdx.x;
    const int w = tid >> 5, lane = tid & 31;
    const int mw = (w & 3) * 32, nw = (w >> 2) * 64;
    const int bm = blockIdx.x * 128;

    if (tid < 128) {
        float s = __ldg(ba + tid);
        if (bb) s += __ldg(bb + tid);
        if (bc) s += __ldg(bc + tid);
        bias_s[tid] = s;
    }

    // lane-constant address pieces
    const u32 aoff = (u32)((mw + (lane & 15)) * APITCH + (lane >> 4) * 16);
    const int wg = lane >> 3, wi = lane & 7;
    const u32 wkoff = (u32)(((wg & 1) * 8 + wi) * WPITCH);
    const u32 wnoff = (u32)((nw + (wg >> 1) * 8) * 2);

    float c[2][8][4];
    #pragma unroll
    for (int mg = 0; mg < 2; mg++)
        #pragma unroll
        for (int nf = 0; nf < 8; nf++)
            #pragma unroll
            for (int q = 0; q < 4; q++) c[mg][nf][q] = 0.f;

    #pragma unroll 1
    for (int seg = 0; seg < nseg; seg++) {
        const u32* Ah = seg ? A1h : A0h;
        const u32* Al = seg ? A1l : A0l;
        const int mat = seg ? mat1 : mat0;

        __syncthreads();   // previous compute done before W overwrite
        {   // stage W hi/lo: 2048 16B units each; unit u: k=u>>4, c16=u&15
            const uint4* sh = reinterpret_cast<const uint4*>(g_wt_hi[mat]);
            const uint4* sl = reinterpret_cast<const uint4*>(g_wt_lo[mat]);
            #pragma unroll
            for (int q = 0; q < 8; q++) {
                int u = q * 256 + tid;
                int kk = u >> 4, c16 = u & 15;
                *reinterpret_cast<uint4*>(smem + SMB_WH + kk * WPITCH + c16 * 16) = sh[u];
                *reinterpret_cast<uint4*>(smem + SMB_WL + kk * WPITCH + c16 * 16) = sl[u];
            }
        }

        #pragma unroll 1
        for (int kc = 0; kc < 8; kc++) {
            __syncthreads();
            {   // stage A chunk: 128 rows x 16 k (bf16) per version
                int r = tid >> 1, h = tid & 1;
                int grow = bm + r;
                uint4 vh = make_uint4(0, 0, 0, 0), vl = make_uint4(0, 0, 0, 0);
                if (grow < M) {
                    size_t idx = (size_t)grow * 16 + kc * 2 + h;
                    vh = reinterpret_cast<const uint4*>(Ah)[idx];
                    vl = reinterpret_cast<const uint4*>(Al)[idx];
                }
                *reinterpret_cast<uint4*>(smem + SMB_AH + r * APITCH + h * 16) = vh;
                *reinterpret_cast<uint4*>(smem + SMB_AL + r * APITCH + h * 16) = vl;
            }
            __syncthreads();

            u32 ah[2][4], al_[2][4];
            #pragma unroll
            for (int mg = 0; mg < 2; mg++) {
                LDMX4(ah[mg],  sb + SMB_AH + aoff + mg * 16 * APITCH);
                LDMX4(al_[mg], sb + SMB_AL + aoff + mg * 16 * APITCH);
            }
            u32 bw[4][4];
            const u32 wko = (u32)(kc * 16 * WPITCH) + wkoff;
            #pragma unroll
            for (int nf = 0; nf < 4; nf++)
                LDMX4T(bw[nf], sb + SMB_WH + wko + wnoff + nf * 32);
            #pragma unroll
            for (int mg = 0; mg < 2; mg++)
                #pragma unroll
                for (int nf = 0; nf < 4; nf++) {
                    MMA(c[mg][2 * nf],     ah[mg],  bw[nf][0], bw[nf][1]);
                    MMA(c[mg][2 * nf + 1], ah[mg],  bw[nf][2], bw[nf][3]);
                    MMA(c[mg][2 * nf],     al_[mg], bw[nf][0], bw[nf][1]);
                    MMA(c[mg][2 * nf + 1], al_[mg], bw[nf][2], bw[nf][3]);
                }
            #pragma unroll
            for (int nf = 0; nf < 4; nf++)
                LDMX4T(bw[nf], sb + SMB_WL + wko + wnoff + nf * 32);
            #pragma unroll
            for (int mg = 0; mg < 2; mg++)
                #pragma unroll
                for (int nf = 0; nf < 4; nf++) {
                    MMA(c[mg][2 * nf],     ah[mg], bw[nf][0], bw[nf][1]);
                    MMA(c[mg][2 * nf + 1], ah[mg], bw[nf][2], bw[nf][3]);
                }
        }
    }

    // ---- epilogue ----
    const int r0 = (lane >> 2);
    const int cb = 2 * (lane & 3);
    #pragma unroll
    for (int mg = 0; mg < 2; mg++) {
        #pragma unroll
        for (int nf = 0; nf < 8; nf++) {
            int col = nw + nf * 8 + cb;
            int rowA = bm + mw + mg * 16 + r0;
            int rowB = rowA + 8;
            float b0 = bias_s[col], b1 = bias_s[col + 1];
            if (mode) {
                float h00 = fmaxf(c[mg][nf][0] + b0, 0.f);
                float h01 = fmaxf(c[mg][nf][1] + b1, 0.f);
                float h10 = fmaxf(c[mg][nf][2] + b0, 0.f);
                float h11 = fmaxf(c[mg][nf][3] + b1, 0.f);
                u32 hi, lo;
                if (rowA < M) {
                    split2(h00, h01, hi, lo);
                    outh[(size_t)rowA * 64 + (col >> 1)] = hi;
                    outl[(size_t)rowA * 64 + (col >> 1)] = lo;
                }
                if (rowB < M) {
                    split2(h10, h11, hi, lo);
                    outh[(size_t)rowB * 64 + (col >> 1)] = hi;
                    outl[(size_t)rowB * 64 + (col >> 1)] = lo;
                }
            } else {
                if (rowA < M)
                    *reinterpret_cast<float2*>(outf + (size_t)rowA * 128 + col) =
                        make_float2(c[mg][nf][0] + b0, c[mg][nf][1] + b1);
                if (rowB < M)
                    *reinterpret_cast<float2*>(outf + (size_t)rowB * 128 + col) =
                        make_float2(c[mg][nf][2] + b0, c[mg][nf][3] + b1);
            }
        }
    }
}

// ---------------------------------------------------------------------------
// Launch: only the h_a branch matters — h_b in the reference is dead code.
// out = (relu(aggr_ba @ wl.T + x_a @ (w0+w1).T + biases)) @ out_w.T + out_b
// ---------------------------------------------------------------------------
extern "C" void kernel_launch(void* const* d_in, const int* in_sizes, int n_in,
                              void* d_out, int out_size) {
    const float* x_a     = (const float*)d_in[0];
    const int*   edge_ba = (const int*)d_in[3];
    const float* c1_w0_w = (const float*)d_in[10];
    const float* c1_w0_b = (const float*)d_in[11];
    const float* c1_wl_w = (const float*)d_in[12];
    const float* c1_wl_b = (const float*)d_in[13];
    const float* c1_w1_w = (const float*)d_in[14];
    const float* c1_w1_b = (const float*)d_in[15];
    const float* out_w   = (const float*)d_in[16];
    const float* out_b   = (const float*)d_in[17];
    float* out = (float*)d_out;

    u32 *ah, *al, *xh, *xl, *h1h, *h1l;
    cudaGetSymbolAddress((void**)&ah, g_ah);
    cudaGetSymbolAddress((void**)&al, g_al);
    cudaGetSymbolAddress((void**)&xh, g_xh);
    cudaGetSymbolAddress((void**)&xl, g_xl);
    cudaGetSymbolAddress((void**)&h1h, g_h1h);
    cudaGetSymbolAddress((void**)&h1l, g_h1l);

    // 1) head init
    init_head_kernel<<<NBLK, 256>>>();
    // 2) fused prep: build ∥ xsplit ∥ wprep
    prep_kernel<<<PB_TOTAL, 256>>>(edge_ba, x_a,
                                   c1_wl_w, c1_w0_w, c1_w1_w, out_w);
    // 3) gather-reduce
    aggregate_kernel<<<(Nn + 7) / 8, 256>>>(x_a);

    cudaFuncSetAttribute(tc_gemm, cudaFuncAttributeMaxDynamicSharedMemorySize, SMB_TOT);
    const int grid = (Nn + 127) / 128;  // 391

    // 4) h1 = relu(aggr @ Wl^T + x_a @ (W0+W1)^T + bias) -> split bf16
    tc_gemm<<<grid, 256, SMB_TOT>>>(ah, al, xh, xl, 0, 1, 2,
                                    c1_wl_b, c1_w0_b, c1_w1_b,
                                    nullptr, h1h, h1l, 1, Nn);
    // 5) out = h1 @ Wout^T + out_b (fp32)
    tc_gemm<<<grid, 256, SMB_TOT>>>(h1h, h1l, nullptr, nullptr, 2, 2, 1,
                                    out_b, nullptr, nullptr,
                                    out, nullptr, nullptr, 0, Nn);
}

// round 10
// speedup vs baseline: 1.6115x; 1.1563x over previous
#include <cuda_runtime.h>
#include <cuda_bf16.h>
#include <cstdint>

#define Nn 50000
#define Hh 128
#define Ee 500000
#define NBLK 196  // ceil(Nn/256)

// fused prep kernel block ranges
#define PB_BUILD  1954                 // ceil(Ee/256)
#define PB_XSPLIT 3125                 // Nn*64/4/256
#define PB_WPREP  192                  // 3*16384/256
#define PB_TOTAL  (PB_BUILD + PB_XSPLIT + PB_WPREP)

typedef unsigned long long u64;
typedef unsigned int u32;

// ---------------------------------------------------------------------------
// Scratch (device globals: no allocation allowed)
// ---------------------------------------------------------------------------
__device__ int g_head[Nn];
__device__ u64 g_link[Ee];
// bf16 hi/lo operand images, packed 2 bf16 per u32 (memory order: even col low)
__device__ u32 g_ah[(size_t)Nn * 64];   // aggr hi
__device__ u32 g_al[(size_t)Nn * 64];   // aggr lo
__device__ u32 g_xh[(size_t)Nn * 64];   // x_a hi
__device__ u32 g_xl[(size_t)Nn * 64];   // x_a lo
__device__ u32 g_h1h[(size_t)Nn * 64];  // h1 hi
__device__ u32 g_h1l[(size_t)Nn * 64];  // h1 lo
// Weights, TRANSPOSED row-major: Wt[k*128 + n] = W[n][k]. 0=Wl, 1=W0+W1, 2=Wout
__device__ unsigned short g_wt_hi[3][16384];
__device__ unsigned short g_wt_lo[3][16384];

// ---------------------------------------------------------------------------
// helpers
// ---------------------------------------------------------------------------
__device__ __forceinline__ u32 smem_u32(const void* p) {
    u32 a;
    asm("{ .reg .u64 t; cvta.to.shared.u64 t, %1; cvt.u32.u64 %0, t; }"
        : "=r"(a) : "l"(p));
    return a;
}
__device__ __forceinline__ void split2(float a, float b, u32& hi, u32& lo) {
    __nv_bfloat16 ha = __float2bfloat16(a), hb = __float2bfloat16(b);
    hi = (u32)__bfloat16_as_ushort(ha) | ((u32)__bfloat16_as_ushort(hb) << 16);
    __nv_bfloat16 la = __float2bfloat16(a - __bfloat162float(ha));
    __nv_bfloat16 lb = __float2bfloat16(b - __bfloat162float(hb));
    lo = (u32)__bfloat16_as_ushort(la) | ((u32)__bfloat16_as_ushort(lb) << 16);
}

#define LDMX4(r, addr) \
    asm volatile("ldmatrix.sync.aligned.m8n8.x4.shared.b16 {%0,%1,%2,%3}, [%4];" \
        : "=r"((r)[0]), "=r"((r)[1]), "=r"((r)[2]), "=r"((r)[3]) : "r"(addr))
#define LDMX4T(r, addr) \
    asm volatile("ldmatrix.sync.aligned.m8n8.x4.trans.shared.b16 {%0,%1,%2,%3}, [%4];" \
        : "=r"((r)[0]), "=r"((r)[1]), "=r"((r)[2]), "=r"((r)[3]) : "r"(addr))
#define MMA(c, a, b0, b1) \
    asm volatile("mma.sync.aligned.m16n8k16.row.col.f32.bf16.bf16.f32 " \
        "{%0,%1,%2,%3},{%4,%5,%6,%7},{%8,%9},{%0,%1,%2,%3};" \
        : "+f"((c)[0]), "+f"((c)[1]), "+f"((c)[2]), "+f"((c)[3]) \
        : "r"((a)[0]), "r"((a)[1]), "r"((a)[2]), "r"((a)[3]), "r"(b0), "r"(b1))
#define CPA16(dst, src) \
    asm volatile("cp.async.ca.shared.global [%0], [%1], 16;" \
                 :: "r"((u32)(dst)), "l"(src) : "memory")
#define CPA_COMMIT() asm volatile("cp.async.commit_group;" ::: "memory")
#define CPA_WAIT0()  asm volatile("cp.async.wait_group 0;" ::: "memory")

// ---------------------------------------------------------------------------
// init heads
// ---------------------------------------------------------------------------
__global__ void init_head_kernel() {
    int i = blockIdx.x * 256 + threadIdx.x;
    if (i < Nn) g_head[i] = -1;
}

// ---------------------------------------------------------------------------
// Fused prep: build linked list ∥ split x_a ∥ weight transpose+split.
// ---------------------------------------------------------------------------
__global__ void prep_kernel(const int* __restrict__ edge,
                            const float* __restrict__ x,
                            const float* __restrict__ wl,
                            const float* __restrict__ w0,
                            const float* __restrict__ w1,
                            const float* __restrict__ wout) {
    int b = blockIdx.x;
    int tid = threadIdx.x;
    if (b < PB_BUILD) {
        int e = b * 256 + tid;
        if (e < Ee) {
            int dst = __ldg(edge + e);
            int src = __ldg(edge + Ee + e);
            int prev = atomicExch(&g_head[dst], e);
            g_link[e] = ((u64)(unsigned)src << 32) | (unsigned)prev;
        }
    } else if (b < PB_BUILD + PB_XSPLIT) {
        size_t t = (size_t)(b - PB_BUILD) * 256 + tid;
        const float4* xp = reinterpret_cast<const float4*>(x) + t * 2;
        float4 v0 = __ldg(xp);
        float4 v1 = __ldg(xp + 1);
        uint4 h, l;
        split2(v0.x, v0.y, h.x, l.x);
        split2(v0.z, v0.w, h.y, l.y);
        split2(v1.x, v1.y, h.z, l.z);
        split2(v1.z, v1.w, h.w, l.w);
        reinterpret_cast<uint4*>(g_xh)[t] = h;
        reinterpret_cast<uint4*>(g_xl)[t] = l;
    } else {
        int i = (b - PB_BUILD - PB_XSPLIT) * 256 + tid;
        int mat = i >> 14;
        int l = i & 16383;
        int k = l >> 7, n = l & 127;
        int src = n * 128 + k;
        float v = (mat == 0) ? __ldg(wl + src)
                : (mat == 1) ? __ldg(w0 + src) + __ldg(w1 + src)
                             : __ldg(wout + src);
        __nv_bfloat16 hb = __float2bfloat16(v);
        g_wt_hi[mat][l] = __bfloat16_as_ushort(hb);
        g_wt_lo[mat][l] =
            __bfloat16_as_ushort(__float2bfloat16(v - __bfloat162float(hb)));
    }
}

// ---------------------------------------------------------------------------
// Gather-reduce: one warp per node walks its list; emits bf16 hi/lo.
// ---------------------------------------------------------------------------
__global__ void aggregate_kernel(const float* __restrict__ x) {
    int n = blockIdx.x * 8 + (threadIdx.x >> 5);
    if (n >= Nn) return;
    int lane = threadIdx.x & 31;
    float4 acc = make_float4(0.f, 0.f, 0.f, 0.f);
    int e = g_head[n];
    while (e != -1) {
        u64 pk = __ldg(g_link + e);
        int src = (int)(pk >> 32);
        e = (int)(unsigned)pk;
        float4 v = *reinterpret_cast<const float4*>(x + (size_t)src * Hh + lane * 4);
        acc.x += v.x; acc.y += v.y; acc.z += v.z; acc.w += v.w;
    }
    u32 h0, l0, h1, l1;
    split2(acc.x, acc.y, h0, l0);
    split2(acc.z, acc.w, h1, l1);
    size_t o = (size_t)n * 64 + lane * 2;
    g_ah[o] = h0; g_ah[o + 1] = h1;
    g_al[o] = l0; g_al[o + 1] = l1;
}

// ---------------------------------------------------------------------------
// Tensor-core GEMM with cp.async double-buffered pipeline.
//   C[M,128] = act( sum_seg A_seg @ W_seg^T + bias )
//   A,W split bf16 hi/lo; Ah@Wh + Ah@Wl + Al@Wh, fp32 accum.
// 256 threads = 8 warps (warp tile 32m x 64n), 128x128 block tile.
// A chunks (16k) double-buffered via cp.async; W resident per segment.
// ---------------------------------------------------------------------------
#define SMB_BIAS 0        // 512 B
#define SMB_A0   512      // buf0: hi 6144 + lo 6144
#define SMB_A1   12800    // buf1: hi 6144 + lo 6144
#define SMB_WH   25088    // 128 x 272
#define SMB_WL   59904    // 128 x 272
#define SMB_TOT  94720
#define APITCH   48
#define ABUF_LO  6144     // lo offset within an A buffer
#define WPITCH   272

__global__ __launch_bounds__(256, 2) void tc_gemm(
    const u32* __restrict__ A0h, const u32* __restrict__ A0l,
    const u32* __restrict__ A1h, const u32* __restrict__ A1l,
    int mat0, int mat1, int nseg,
    const float* __restrict__ ba, const float* __restrict__ bb,
    const float* __restrict__ bc,
    float* __restrict__ outf, u32* __restrict__ outh, u32* __restrict__ outl,
    int mode, int M)
{
    extern __shared__ __align__(16) char smem[];
    const u32 sb = smem_u32(smem);
    float* bias_s = reinterpret_cast<float*>(smem + SMB_BIAS);

    const int tid = threadIdx.x;
    const int w = tid >> 5, lane = tid & 31;
    const int mw = (w & 3) * 32, nw = (w >> 2) * 64;
    const int bm = blockIdx.x * 128;

    // boundary block: pre-zero A buffers; cp.async never touches invalid rows,
    // so their zeros persist across all chunks/segments.
    if (bm + 128 > M) {
        #pragma unroll
        for (int q = 0; q < 6; q++)
            reinterpret_cast<uint4*>(smem + SMB_A0)[q * 256 + tid] =
                make_uint4(0, 0, 0, 0);
    }
    if (tid < 128) {
        float s = __ldg(ba + tid);
        if (bb) s += __ldg(bb + tid);
        if (bc) s += __ldg(bc + tid);
        bias_s[tid] = s;
    }

    // lane-constant address pieces
    const u32 aoff = (u32)((mw + (lane & 15)) * APITCH + (lane >> 4) * 16);
    const int wg = lane >> 3, wi = lane & 7;
    const u32 wkoff = (u32)(((wg & 1) * 8 + wi) * WPITCH);
    const u32 wnoff = (u32)((nw + (wg >> 1) * 8) * 2);

    // per-thread A-stage mapping: row = tid>>1, h = tid&1 (16B unit within chunk)
    const int ar = tid >> 1, ahalf = tid & 1;
    const bool avalid = (bm + ar) < M;
    const u32 adst_off = (u32)(ar * APITCH + ahalf * 16);

    float c[2][8][4];
    #pragma unroll
    for (int mg = 0; mg < 2; mg++)
        #pragma unroll
        for (int nf = 0; nf < 8; nf++)
            #pragma unroll
            for (int q = 0; q < 4; q++) c[mg][nf][q] = 0.f;

    #pragma unroll 1
    for (int seg = 0; seg < nseg; seg++) {
        const u32* Ah = seg ? A1h : A0h;
        const u32* Al = seg ? A1l : A0l;
        const int mat = seg ? mat1 : mat0;

        __syncthreads();   // prior compute done before W / buf overwrite

        // ---- async stage W hi/lo (full segment) ----
        {
            const char* sh = reinterpret_cast<const char*>(g_wt_hi[mat]);
            const char* sl = reinterpret_cast<const char*>(g_wt_lo[mat]);
            #pragma unroll
            for (int q = 0; q < 8; q++) {
                int u = q * 256 + tid;
                int kk = u >> 4, c16 = u & 15;
                u32 d = (u32)(kk * WPITCH + c16 * 16);
                CPA16(sb + SMB_WH + d, sh + (size_t)u * 16);
                CPA16(sb + SMB_WL + d, sl + (size_t)u * 16);
            }
        }
        // ---- async stage A chunk 0 into buf0 ----
        if (avalid) {
            size_t su = (size_t)(bm + ar) * 16 + ahalf;   // kc=0
            CPA16(sb + SMB_A0 + adst_off,
                  reinterpret_cast<const char*>(Ah) + su * 16);
            CPA16(sb + SMB_A0 + ABUF_LO + adst_off,
                  reinterpret_cast<const char*>(Al) + su * 16);
        }
        CPA_COMMIT();

        #pragma unroll 1
        for (int kc = 0; kc < 8; kc++) {
            CPA_WAIT0();
            __syncthreads();

            // prefetch next chunk into the other buffer
            if (kc < 7) {
                u32 nbuf = (kc + 1) & 1;
                u32 dstb = sb + (nbuf ? SMB_A1 : SMB_A0);
                if (avalid) {
                    size_t su = (size_t)(bm + ar) * 16 + (kc + 1) * 2 + ahalf;
                    CPA16(dstb + adst_off,
                          reinterpret_cast<const char*>(Ah) + su * 16);
                    CPA16(dstb + ABUF_LO + adst_off,
                          reinterpret_cast<const char*>(Al) + su * 16);
                }
                CPA_COMMIT();
            }

            // ---- compute from buf[kc&1] ----
            const u32 abase = sb + ((kc & 1) ? SMB_A1 : SMB_A0);
            u32 ah[2][4], al_[2][4];
            #pragma unroll
            for (int mg = 0; mg < 2; mg++) {
                LDMX4(ah[mg],  abase + aoff + mg * 16 * APITCH);
                LDMX4(al_[mg], abase + ABUF_LO + aoff + mg * 16 * APITCH);
            }
            u32 bw[4][4];
            const u32 wko = (u32)(kc * 16 * WPITCH) + wkoff;
            #pragma unroll
            for (int nf = 0; nf < 4; nf++)
                LDMX4T(bw[nf], sb + SMB_WH + wko + wnoff + nf * 32);
            #pragma unroll
            for (int mg = 0; mg < 2; mg++)
                #pragma unroll
                for (int nf = 0; nf < 4; nf++) {
                    MMA(c[mg][2 * nf],     ah[mg],  bw[nf][0], bw[nf][1]);
                    MMA(c[mg][2 * nf + 1], ah[mg],  bw[nf][2], bw[nf][3]);
                    MMA(c[mg][2 * nf],     al_[mg], bw[nf][0], bw[nf][1]);
                    MMA(c[mg][2 * nf + 1], al_[mg], bw[nf][2], bw[nf][3]);
                }
            #pragma unroll
            for (int nf = 0; nf < 4; nf++)
                LDMX4T(bw[nf], sb + SMB_WL + wko + wnoff + nf * 32);
            #pragma unroll
            for (int mg = 0; mg < 2; mg++)
                #pragma unroll
                for (int nf = 0; nf < 4; nf++) {
                    MMA(c[mg][2 * nf],     ah[mg], bw[nf][0], bw[nf][1]);
                    MMA(c[mg][2 * nf + 1], ah[mg], bw[nf][2], bw[nf][3]);
                }
        }
    }

    // ---- epilogue ----
    const int r0 = (lane >> 2);
    const int cb = 2 * (lane & 3);
    #pragma unroll
    for (int mg = 0; mg < 2; mg++) {
        #pragma unroll
        for (int nf = 0; nf < 8; nf++) {
            int col = nw + nf * 8 + cb;
            int rowA = bm + mw + mg * 16 + r0;
            int rowB = rowA + 8;
            float b0 = bias_s[col], b1 = bias_s[col + 1];
            if (mode) {
                float h00 = fmaxf(c[mg][nf][0] + b0, 0.f);
                float h01 = fmaxf(c[mg][nf][1] + b1, 0.f);
                float h10 = fmaxf(c[mg][nf][2] + b0, 0.f);
                float h11 = fmaxf(c[mg][nf][3] + b1, 0.f);
                u32 hi, lo;
                if (rowA < M) {
                    split2(h00, h01, hi, lo);
                    outh[(size_t)rowA * 64 + (col >> 1)] = hi;
                    outl[(size_t)rowA * 64 + (col >> 1)] = lo;
                }
                if (rowB < M) {
                    split2(h10, h11, hi, lo);
                    outh[(size_t)rowB * 64 + (col >> 1)] = hi;
                    outl[(size_t)rowB * 64 + (col >> 1)] = lo;
                }
            } else {
                if (rowA < M)
                    *reinterpret_cast<float2*>(outf + (size_t)rowA * 128 + col) =
                        make_float2(c[mg][nf][0] + b0, c[mg][nf][1] + b1);
                if (rowB < M)
                    *reinterpret_cast<float2*>(outf + (size_t)rowB * 128 + col) =
                        make_float2(c[mg][nf][2] + b0, c[mg][nf][3] + b1);
            }
        }
    }
}

// ---------------------------------------------------------------------------
// Launch: only the h_a branch matters — h_b in the reference is dead code.
// out = (relu(aggr_ba @ wl.T + x_a @ (w0+w1).T + biases)) @ out_w.T + out_b
// ---------------------------------------------------------------------------
extern "C" void kernel_launch(void* const* d_in, const int* in_sizes, int n_in,
                              void* d_out, int out_size) {
    const float* x_a     = (const float*)d_in[0];
    const int*   edge_ba = (const int*)d_in[3];
    const float* c1_w0_w = (const float*)d_in[10];
    const float* c1_w0_b = (const float*)d_in[11];
    const float* c1_wl_w = (const float*)d_in[12];
    const float* c1_wl_b = (const float*)d_in[13];
    const float* c1_w1_w = (const float*)d_in[14];
    const float* c1_w1_b = (const float*)d_in[15];
    const float* out_w   = (const float*)d_in[16];
    const float* out_b   = (const float*)d_in[17];
    float* out = (float*)d_out;

    u32 *ah, *al, *xh, *xl, *h1h, *h1l;
    cudaGetSymbolAddress((void**)&ah, g_ah);
    cudaGetSymbolAddress((void**)&al, g_al);
    cudaGetSymbolAddress((void**)&xh, g_xh);
    cudaGetSymbolAddress((void**)&xl, g_xl);
    cudaGetSymbolAddress((void**)&h1h, g_h1h);
    cudaGetSymbolAddress((void**)&h1l, g_h1l);

    // 1) head init
    init_head_kernel<<<NBLK, 256>>>();
    // 2) fused prep: build ∥ xsplit ∥ wprep
    prep_kernel<<<PB_TOTAL, 256>>>(edge_ba, x_a,
                                   c1_wl_w, c1_w0_w, c1_w1_w, out_w);
    // 3) gather-reduce
    aggregate_kernel<<<(Nn + 7) / 8, 256>>>(x_a);

    cudaFuncSetAttribute(tc_gemm, cudaFuncAttributeMaxDynamicSharedMemorySize, SMB_TOT);
    const int grid = (Nn + 127) / 128;  // 391

    // 4) h1 = relu(aggr @ Wl^T + x_a @ (W0+W1)^T + bias) -> split bf16
    tc_gemm<<<grid, 256, SMB_TOT>>>(ah, al, xh, xl, 0, 1, 2,
                                    c1_wl_b, c1_w0_b, c1_w1_b,
                                    nullptr, h1h, h1l, 1, Nn);
    // 5) out = h1 @ Wout^T + out_b (fp32)
    tc_gemm<<<grid, 256, SMB_TOT>>>(h1h, h1l, nullptr, nullptr, 2, 2, 1,
                                    out_b, nullptr, nullptr,
                                    out, nullptr, nullptr, 0, Nn);
}